// round 1
// baseline (speedup 1.0000x reference)
#include <cuda_runtime.h>
#include <math_constants.h>

// Problem dims (fixed by the reference)
#define B_SZ   4
#define S_LEN  4096
#define D_DIM  1024
#define M_QKV  (B_SZ * S_LEN)   // 16384

// SGEMM tiling
#define BM 128
#define BN 128
#define BK 8
#define TM 8
#define TN 8
// threads = (BM/TM)*(BN/TN) = 256

// Scratch (allocation-free rule: __device__ globals)
__device__ float g_q[(size_t)B_SZ * S_LEN * D_DIM];          // 64 MB
__device__ float g_k[(size_t)B_SZ * S_LEN * D_DIM];          // 64 MB
__device__ float g_v[(size_t)B_SZ * S_LEN * D_DIM];          // 64 MB
__device__ float g_p[(size_t)B_SZ * S_LEN * S_LEN];          // 256 MB (scores/probs)

// ---------------------------------------------------------------------------
// C[M,N] = alpha * A[M,K] * B[N,K]^T (+ bias[N]);  lda=K, ldb=K, ldc=N
// blockIdx.x -> N tile, blockIdx.y -> M tile. All dims multiples of tile sizes.
// ---------------------------------------------------------------------------
__device__ __forceinline__ void sgemm_nt_body(
    const float* __restrict__ A, const float* __restrict__ Bm,
    const float* __restrict__ bias, float* __restrict__ C,
    int N, int K, float alpha)
{
    __shared__ float As[BK][BM];
    __shared__ float Bs[BK][BN];

    const int tid = threadIdx.x;
    const int tc  = tid & 15;   // 0..15  (N dir)
    const int tr  = tid >> 4;   // 0..15  (M dir)

    const int rowA = blockIdx.y * BM;
    const int colB = blockIdx.x * BN;

    // Global load mapping: 1 float4 per thread for each of A,B per BK-slab.
    const int lRow = tid >> 1;          // 0..127
    const int lCol = (tid & 1) * 4;     // 0 or 4
    const float* Aptr = A  + (size_t)(rowA + lRow) * K + lCol;
    const float* Bptr = Bm + (size_t)(colB + lRow) * K + lCol;

    float acc[TM][TN] = {};

    for (int k0 = 0; k0 < K; k0 += BK) {
        float4 av = *reinterpret_cast<const float4*>(Aptr + k0);
        float4 bv = *reinterpret_cast<const float4*>(Bptr + k0);
        As[lCol + 0][lRow] = av.x;
        As[lCol + 1][lRow] = av.y;
        As[lCol + 2][lRow] = av.z;
        As[lCol + 3][lRow] = av.w;
        Bs[lCol + 0][lRow] = bv.x;
        Bs[lCol + 1][lRow] = bv.y;
        Bs[lCol + 2][lRow] = bv.z;
        Bs[lCol + 3][lRow] = bv.w;
        __syncthreads();

        #pragma unroll
        for (int k = 0; k < BK; ++k) {
            float4 a0 = *reinterpret_cast<const float4*>(&As[k][tr * TM]);
            float4 a1 = *reinterpret_cast<const float4*>(&As[k][tr * TM + 4]);
            float4 b0 = *reinterpret_cast<const float4*>(&Bs[k][tc * TN]);
            float4 b1 = *reinterpret_cast<const float4*>(&Bs[k][tc * TN + 4]);
            float ra[TM] = {a0.x, a0.y, a0.z, a0.w, a1.x, a1.y, a1.z, a1.w};
            float rb[TN] = {b0.x, b0.y, b0.z, b0.w, b1.x, b1.y, b1.z, b1.w};
            #pragma unroll
            for (int i = 0; i < TM; ++i)
                #pragma unroll
                for (int j = 0; j < TN; ++j)
                    acc[i][j] = fmaf(ra[i], rb[j], acc[i][j]);
        }
        __syncthreads();
    }

    // Epilogue: vectorized coalesced stores
    #pragma unroll
    for (int i = 0; i < TM; ++i) {
        size_t r = (size_t)(rowA + tr * TM + i);
        float* crow = C + r * (size_t)N + colB + tc * TN;
        float4 v0, v1;
        v0.x = acc[i][0] * alpha; v0.y = acc[i][1] * alpha;
        v0.z = acc[i][2] * alpha; v0.w = acc[i][3] * alpha;
        v1.x = acc[i][4] * alpha; v1.y = acc[i][5] * alpha;
        v1.z = acc[i][6] * alpha; v1.w = acc[i][7] * alpha;
        if (bias) {
            const float* brow = bias + colB + tc * TN;
            float4 bb0 = *reinterpret_cast<const float4*>(brow);
            float4 bb1 = *reinterpret_cast<const float4*>(brow + 4);
            v0.x += bb0.x; v0.y += bb0.y; v0.z += bb0.z; v0.w += bb0.w;
            v1.x += bb1.x; v1.y += bb1.y; v1.z += bb1.z; v1.w += bb1.w;
        }
        *reinterpret_cast<float4*>(crow)     = v0;
        *reinterpret_cast<float4*>(crow + 4) = v1;
    }
}

// ---------------------------------------------------------------------------
// C[M,N] = A[M,K] * B[K,N];  lda=K, ldb=N, ldc=N
// ---------------------------------------------------------------------------
__device__ __forceinline__ void sgemm_nn_body(
    const float* __restrict__ A, const float* __restrict__ Bm,
    float* __restrict__ C, int N, int K)
{
    __shared__ float As[BK][BM];
    __shared__ float Bs[BK][BN];

    const int tid = threadIdx.x;
    const int tc  = tid & 15;
    const int tr  = tid >> 4;

    const int rowA = blockIdx.y * BM;
    const int colB = blockIdx.x * BN;

    const int laRow = tid >> 1;
    const int laCol = (tid & 1) * 4;
    const float* Aptr = A + (size_t)(rowA + laRow) * K + laCol;

    const int lbRow = tid >> 5;          // 0..7   (k)
    const int lbCol = (tid & 31) * 4;    // 0..124 (n)
    const float* Bptr = Bm + (size_t)lbRow * N + colB + lbCol;

    float acc[TM][TN] = {};

    for (int k0 = 0; k0 < K; k0 += BK) {
        float4 av = *reinterpret_cast<const float4*>(Aptr + k0);
        float4 bv = *reinterpret_cast<const float4*>(Bptr + (size_t)k0 * N);
        As[laCol + 0][laRow] = av.x;
        As[laCol + 1][laRow] = av.y;
        As[laCol + 2][laRow] = av.z;
        As[laCol + 3][laRow] = av.w;
        *reinterpret_cast<float4*>(&Bs[lbRow][lbCol]) = bv;
        __syncthreads();

        #pragma unroll
        for (int k = 0; k < BK; ++k) {
            float4 a0 = *reinterpret_cast<const float4*>(&As[k][tr * TM]);
            float4 a1 = *reinterpret_cast<const float4*>(&As[k][tr * TM + 4]);
            float4 b0 = *reinterpret_cast<const float4*>(&Bs[k][tc * TN]);
            float4 b1 = *reinterpret_cast<const float4*>(&Bs[k][tc * TN + 4]);
            float ra[TM] = {a0.x, a0.y, a0.z, a0.w, a1.x, a1.y, a1.z, a1.w};
            float rb[TN] = {b0.x, b0.y, b0.z, b0.w, b1.x, b1.y, b1.z, b1.w};
            #pragma unroll
            for (int i = 0; i < TM; ++i)
                #pragma unroll
                for (int j = 0; j < TN; ++j)
                    acc[i][j] = fmaf(ra[i], rb[j], acc[i][j]);
        }
        __syncthreads();
    }

    #pragma unroll
    for (int i = 0; i < TM; ++i) {
        size_t r = (size_t)(rowA + tr * TM + i);
        float* crow = C + r * (size_t)N + colB + tc * TN;
        float4 v0, v1;
        v0.x = acc[i][0]; v0.y = acc[i][1]; v0.z = acc[i][2]; v0.w = acc[i][3];
        v1.x = acc[i][4]; v1.y = acc[i][5]; v1.z = acc[i][6]; v1.w = acc[i][7];
        *reinterpret_cast<float4*>(crow)     = v0;
        *reinterpret_cast<float4*>(crow + 4) = v1;
    }
}

// ---------------------------------------------------------------------------
// Kernels
// ---------------------------------------------------------------------------
__global__ __launch_bounds__(256) void qkv_kernel(
    const float* __restrict__ x,
    const float* __restrict__ Wq, const float* __restrict__ bq,
    const float* __restrict__ Wk, const float* __restrict__ bk,
    const float* __restrict__ Wv, const float* __restrict__ bv)
{
    const float* W; const float* bias; float* C;
    if (blockIdx.z == 0)      { W = Wq; bias = bq; C = g_q; }
    else if (blockIdx.z == 1) { W = Wk; bias = bk; C = g_k; }
    else                      { W = Wv; bias = bv; C = g_v; }
    sgemm_nt_body(x, W, bias, C, D_DIM, D_DIM, 1.0f);
}

__global__ __launch_bounds__(256) void scores_kernel()
{
    const int b = blockIdx.z;
    const float* q = g_q + (size_t)b * S_LEN * D_DIM;
    const float* k = g_k + (size_t)b * S_LEN * D_DIM;
    float*       p = g_p + (size_t)b * S_LEN * S_LEN;
    sgemm_nt_body(q, k, nullptr, p, S_LEN, D_DIM, 0.03125f);  // 1/sqrt(1024)
}

__global__ __launch_bounds__(256) void softmax_kernel()
{
    const size_t row = blockIdx.x;
    float* p = g_p + row * (size_t)S_LEN;
    const int tid  = threadIdx.x;
    const int lane = tid & 31;
    const int wid  = tid >> 5;

    float4 v[4];
    float mx = -CUDART_INF_F;
    #pragma unroll
    for (int i = 0; i < 4; ++i) {
        v[i] = reinterpret_cast<float4*>(p)[tid + i * 256];
        mx = fmaxf(mx, fmaxf(fmaxf(v[i].x, v[i].y), fmaxf(v[i].z, v[i].w)));
    }
    #pragma unroll
    for (int o = 16; o > 0; o >>= 1)
        mx = fmaxf(mx, __shfl_xor_sync(0xFFFFFFFFu, mx, o));

    __shared__ float smax[8];
    __shared__ float ssum[8];
    __shared__ float sbc[2];
    if (lane == 0) smax[wid] = mx;
    __syncthreads();
    if (tid == 0) {
        float m = smax[0];
        #pragma unroll
        for (int i = 1; i < 8; ++i) m = fmaxf(m, smax[i]);
        sbc[0] = m;
    }
    __syncthreads();
    mx = sbc[0];

    float sum = 0.0f;
    #pragma unroll
    for (int i = 0; i < 4; ++i) {
        v[i].x = __expf(v[i].x - mx);
        v[i].y = __expf(v[i].y - mx);
        v[i].z = __expf(v[i].z - mx);
        v[i].w = __expf(v[i].w - mx);
        sum += v[i].x + v[i].y + v[i].z + v[i].w;
    }
    #pragma unroll
    for (int o = 16; o > 0; o >>= 1)
        sum += __shfl_xor_sync(0xFFFFFFFFu, sum, o);
    if (lane == 0) ssum[wid] = sum;
    __syncthreads();
    if (tid == 0) {
        float s = 0.0f;
        #pragma unroll
        for (int i = 0; i < 8; ++i) s += ssum[i];
        sbc[1] = 1.0f / s;
    }
    __syncthreads();
    const float inv = sbc[1];

    #pragma unroll
    for (int i = 0; i < 4; ++i) {
        v[i].x *= inv; v[i].y *= inv; v[i].z *= inv; v[i].w *= inv;
        reinterpret_cast<float4*>(p)[tid + i * 256] = v[i];
    }
}

__global__ __launch_bounds__(256) void pv_kernel(float* __restrict__ out)
{
    const int b = blockIdx.z;
    const float* p = g_p + (size_t)b * S_LEN * S_LEN;
    const float* v = g_v + (size_t)b * S_LEN * D_DIM;
    float*       o = out + (size_t)b * S_LEN * D_DIM;
    sgemm_nn_body(p, v, o, D_DIM, S_LEN);
}

// ---------------------------------------------------------------------------
extern "C" void kernel_launch(void* const* d_in, const int* in_sizes, int n_in,
                              void* d_out, int out_size)
{
    const float* x  = (const float*)d_in[0];
    const float* Wq = (const float*)d_in[1];
    const float* bq = (const float*)d_in[2];
    const float* Wk = (const float*)d_in[3];
    const float* bk = (const float*)d_in[4];
    const float* Wv = (const float*)d_in[5];
    const float* bv = (const float*)d_in[6];
    float* out = (float*)d_out;

    dim3 blk(256);

    dim3 g_qkv(D_DIM / BN, M_QKV / BM, 3);              // 8 x 128 x 3
    qkv_kernel<<<g_qkv, blk>>>(x, Wq, bq, Wk, bk, Wv, bv);

    dim3 g_sc(S_LEN / BN, S_LEN / BM, B_SZ);            // 32 x 32 x 4
    scores_kernel<<<g_sc, blk>>>();

    softmax_kernel<<<B_SZ * S_LEN, blk>>>();            // 16384 rows

    dim3 g_pv(D_DIM / BN, S_LEN / BM, B_SZ);            // 8 x 32 x 4
    pv_kernel<<<g_pv, blk>>>(out);
}

// round 5
// speedup vs baseline: 2.3116x; 2.3116x over previous
#include <cuda_runtime.h>
#include <cuda_bf16.h>
#include <cstdint>
#include <math_constants.h>

#define B_SZ   4
#define S_LEN  4096
#define D_DIM  1024
#define M_QKV  (B_SZ * S_LEN)   // 16384

// ---------------------------------------------------------------------------
// Scratch (__device__ globals; allocation-free rule)
// ---------------------------------------------------------------------------
__device__ __nv_bfloat16 g_x_hi[(size_t)M_QKV * D_DIM];
__device__ __nv_bfloat16 g_x_lo[(size_t)M_QKV * D_DIM];
__device__ __nv_bfloat16 g_wq_hi[(size_t)D_DIM * D_DIM];
__device__ __nv_bfloat16 g_wq_lo[(size_t)D_DIM * D_DIM];
__device__ __nv_bfloat16 g_wk_hi[(size_t)D_DIM * D_DIM];
__device__ __nv_bfloat16 g_wk_lo[(size_t)D_DIM * D_DIM];
__device__ __nv_bfloat16 g_wv_hi[(size_t)D_DIM * D_DIM];
__device__ __nv_bfloat16 g_wv_lo[(size_t)D_DIM * D_DIM];
__device__ __nv_bfloat16 g_q_hi[(size_t)M_QKV * D_DIM];
__device__ __nv_bfloat16 g_q_lo[(size_t)M_QKV * D_DIM];
__device__ __nv_bfloat16 g_k_hi[(size_t)M_QKV * D_DIM];
__device__ __nv_bfloat16 g_k_lo[(size_t)M_QKV * D_DIM];
__device__ __nv_bfloat16 g_vt_hi[(size_t)B_SZ * D_DIM * S_LEN];  // [B][D][S]
__device__ __nv_bfloat16 g_vt_lo[(size_t)B_SZ * D_DIM * S_LEN];
__device__ float         g_s[(size_t)B_SZ * S_LEN * S_LEN];      // fp32 scores
__device__ __nv_bfloat16 g_p_hi[(size_t)B_SZ * S_LEN * S_LEN];
__device__ __nv_bfloat16 g_p_lo[(size_t)B_SZ * S_LEN * S_LEN];

// ---------------------------------------------------------------------------
// helpers
// ---------------------------------------------------------------------------
__device__ __forceinline__ uint32_t smem_u32(const void* p) {
    uint32_t a;
    asm("{ .reg .u64 t; cvta.to.shared.u64 t, %1; cvt.u32.u64 %0, t; }"
        : "=r"(a) : "l"(p));
    return a;
}

__device__ __forceinline__ void cp16(uint32_t dst, const void* src) {
    asm volatile("cp.async.cg.shared.global [%0], [%1], 16;"
                 :: "r"(dst), "l"(src) : "memory");
}
#define CP_COMMIT() asm volatile("cp.async.commit_group;" ::: "memory")

__device__ __forceinline__ void ldmx4(uint32_t& r0, uint32_t& r1,
                                      uint32_t& r2, uint32_t& r3, uint32_t addr) {
    asm volatile("ldmatrix.sync.aligned.m8n8.x4.shared.b16 {%0,%1,%2,%3}, [%4];"
                 : "=r"(r0), "=r"(r1), "=r"(r2), "=r"(r3) : "r"(addr));
}

__device__ __forceinline__ void mma_bf16(float& c0, float& c1, float& c2, float& c3,
                                         uint32_t a0, uint32_t a1, uint32_t a2, uint32_t a3,
                                         uint32_t b0, uint32_t b1) {
    asm volatile(
        "mma.sync.aligned.m16n8k16.row.col.f32.bf16.bf16.f32 "
        "{%0,%1,%2,%3}, {%4,%5,%6,%7}, {%8,%9}, {%0,%1,%2,%3};"
        : "+f"(c0), "+f"(c1), "+f"(c2), "+f"(c3)
        : "r"(a0), "r"(a1), "r"(a2), "r"(a3), "r"(b0), "r"(b1));
}

__device__ __forceinline__ void split2(float f, __nv_bfloat16& h, __nv_bfloat16& l) {
    h = __float2bfloat16(f);
    l = __float2bfloat16(f - __bfloat162float(h));
}

// ---------------------------------------------------------------------------
// GEMM: C[128,128] per CTA = sum_K (Ah+Al)[M,K] * (Bh+Bl)[N,K]^T
// 8 warps (2x4), warp tile 64x32, BK=32, 3-stage cp.async pipeline.
// SMEM tile: 128 rows x 32 bf16, padded row stride 80B.
// MODE 0: qkv (z: 0=q,1=k,2=v), 1: scores, 2: pv
// ---------------------------------------------------------------------------
#define ROW_B   80
#define TILE_B  (128 * ROW_B)        // 10240
#define STAGE_B (4 * TILE_B)         // 40960  (Ah, Al, Bh, Bl)
#define NSTAGE  3
#define SMEM_TOTAL (NSTAGE * STAGE_B)  // 122880

template <int MODE>
__global__ __launch_bounds__(256, 1)
void mm_kernel(const float* __restrict__ bq, const float* __restrict__ bk,
               const float* __restrict__ bv, float* __restrict__ out)
{
    extern __shared__ char smem[];
    const uint32_t sb = smem_u32(smem);
    const int tid  = threadIdx.x;
    const int wid  = tid >> 5;
    const int lane = tid & 31;
    const int bx = blockIdx.x, by = blockIdx.y, z = blockIdx.z;

    const int rowA = by * 128;
    const int rowB = bx * 128;

    const __nv_bfloat16 *Ah, *Al, *Bh, *Bl;
    int K;
    if (MODE == 0) {
        Ah = g_x_hi; Al = g_x_lo;
        if (z == 0)      { Bh = g_wq_hi; Bl = g_wq_lo; }
        else if (z == 1) { Bh = g_wk_hi; Bl = g_wk_lo; }
        else             { Bh = g_wv_hi; Bl = g_wv_lo; }
        K = D_DIM;
    } else if (MODE == 1) {
        Ah = g_q_hi + (size_t)z * S_LEN * D_DIM;
        Al = g_q_lo + (size_t)z * S_LEN * D_DIM;
        Bh = g_k_hi + (size_t)z * S_LEN * D_DIM;
        Bl = g_k_lo + (size_t)z * S_LEN * D_DIM;
        K = D_DIM;
    } else {
        Ah = g_p_hi + (size_t)z * S_LEN * S_LEN;
        Al = g_p_lo + (size_t)z * S_LEN * S_LEN;
        Bh = g_vt_hi + (size_t)z * D_DIM * S_LEN;
        Bl = g_vt_lo + (size_t)z * D_DIM * S_LEN;
        K = S_LEN;
    }

    const int nslab = K >> 5;          // K/32

    // ------------------ loader ------------------
    const int lr = tid >> 1;           // 0..127
    const int sp = (tid & 1) * 2;      // seg pair: {0,1} or {2,3}
    auto load_slab = [&](int i) {
        const uint32_t stage = sb + (uint32_t)(i % NSTAGE) * STAGE_B;
        const size_t koff = (size_t)i * 32;
        #pragma unroll
        for (int t = 0; t < 4; ++t) {
            const __nv_bfloat16* p = (t == 0) ? Ah : (t == 1) ? Al : (t == 2) ? Bh : Bl;
            const int ro = (t < 2) ? rowA : rowB;
            const __nv_bfloat16* src = p + (size_t)(ro + lr) * K + koff + sp * 8;
            const uint32_t dst = stage + (uint32_t)t * TILE_B + (uint32_t)lr * ROW_B
                                 + (uint32_t)sp * 16;
            cp16(dst,      src);
            cp16(dst + 16, src + 8);
        }
        CP_COMMIT();
    };

    // ------------------ fragments ------------------
    const int warp_m = wid >> 2;       // 0..1
    const int warp_n = wid & 3;        // 0..3
    const int mat    = lane >> 3;      // 0..3
    const int mrow   = lane & 7;

    // A ldmatrix thread offsets (within 16x16 tile): row=(mat&1)*8+mrow, col16=mat>>1
    const uint32_t a_off = (uint32_t)(((mat & 1) * 8 + mrow) * ROW_B + (mat >> 1) * 16);
    // B: row=(mat>>1)*8+mrow, col16=mat&1
    const uint32_t b_off = (uint32_t)(((mat >> 1) * 8 + mrow) * ROW_B + (mat & 1) * 16);

    float acc[4][4][4];
    #pragma unroll
    for (int mi = 0; mi < 4; ++mi)
        #pragma unroll
        for (int ni = 0; ni < 4; ++ni)
            #pragma unroll
            for (int r = 0; r < 4; ++r) acc[mi][ni][r] = 0.0f;

    load_slab(0);
    load_slab(1);

    for (int i = 0; i < nslab; ++i) {
        if (i + 1 < nslab) asm volatile("cp.async.wait_group 1;" ::: "memory");
        else               asm volatile("cp.async.wait_group 0;" ::: "memory");
        __syncthreads();

        if (i + 2 < nslab) load_slab(i + 2);   // stage (i+2)%3 == (i-1)%3, free

        const uint32_t stage = sb + (uint32_t)(i % NSTAGE) * STAGE_B;
        const uint32_t aBase = stage + (uint32_t)(warp_m * 64) * ROW_B;
        const uint32_t bBase = stage + 2 * TILE_B + (uint32_t)(warp_n * 32) * ROW_B;

        #pragma unroll
        for (int ks = 0; ks < 2; ++ks) {
            uint32_t ah[4][4], al[4][4], bh[4][2], bl[4][2];
            #pragma unroll
            for (int mi = 0; mi < 4; ++mi) {
                uint32_t ad = aBase + (uint32_t)(mi * 16) * ROW_B + (uint32_t)ks * 32 + a_off;
                ldmx4(ah[mi][0], ah[mi][1], ah[mi][2], ah[mi][3], ad);
                ldmx4(al[mi][0], al[mi][1], al[mi][2], al[mi][3], ad + TILE_B);
            }
            #pragma unroll
            for (int n2 = 0; n2 < 2; ++n2) {
                uint32_t bd = bBase + (uint32_t)(n2 * 16) * ROW_B + (uint32_t)ks * 32 + b_off;
                ldmx4(bh[n2 * 2][0], bh[n2 * 2][1], bh[n2 * 2 + 1][0], bh[n2 * 2 + 1][1], bd);
                ldmx4(bl[n2 * 2][0], bl[n2 * 2][1], bl[n2 * 2 + 1][0], bl[n2 * 2 + 1][1], bd + TILE_B);
            }
            #pragma unroll
            for (int mi = 0; mi < 4; ++mi)
                #pragma unroll
                for (int ni = 0; ni < 4; ++ni) {
                    float* c = acc[mi][ni];
                    mma_bf16(c[0], c[1], c[2], c[3],
                             ah[mi][0], ah[mi][1], ah[mi][2], ah[mi][3],
                             bh[ni][0], bh[ni][1]);
                    mma_bf16(c[0], c[1], c[2], c[3],
                             ah[mi][0], ah[mi][1], ah[mi][2], ah[mi][3],
                             bl[ni][0], bl[ni][1]);
                    mma_bf16(c[0], c[1], c[2], c[3],
                             al[mi][0], al[mi][1], al[mi][2], al[mi][3],
                             bh[ni][0], bh[ni][1]);
                }
        }
        __syncthreads();
    }

    // ------------------ epilogue (from registers) ------------------
    const float* bias = (MODE == 0) ? ((z == 0) ? bq : (z == 1) ? bk : bv) : nullptr;
    __nv_bfloat16 *dh = nullptr, *dl = nullptr;
    if (MODE == 0 && z == 0) { dh = g_q_hi; dl = g_q_lo; }
    if (MODE == 0 && z == 1) { dh = g_k_hi; dl = g_k_lo; }

    #pragma unroll
    for (int mi = 0; mi < 4; ++mi) {
        #pragma unroll
        for (int ni = 0; ni < 4; ++ni) {
            #pragma unroll
            for (int h = 0; h < 2; ++h) {
                const int row_g = rowA + warp_m * 64 + mi * 16 + (lane >> 2) + h * 8;
                const int col_g = rowB + warp_n * 32 + ni * 8 + 2 * (lane & 3);
                float f0 = acc[mi][ni][h * 2];
                float f1 = acc[mi][ni][h * 2 + 1];

                if (MODE == 0) {
                    f0 += bias[col_g];
                    f1 += bias[col_g + 1];
                    __nv_bfloat16 h0, l0, h1, l1;
                    split2(f0, h0, l0);
                    split2(f1, h1, l1);
                    if (z < 2) {
                        __nv_bfloat162 ph; ph.x = h0; ph.y = h1;
                        __nv_bfloat162 pl; pl.x = l0; pl.y = l1;
                        size_t o = (size_t)row_g * D_DIM + col_g;
                        *reinterpret_cast<__nv_bfloat162*>(&dh[o]) = ph;
                        *reinterpret_cast<__nv_bfloat162*>(&dl[o]) = pl;
                    } else {
                        const int b = row_g >> 12;
                        const int s = row_g & (S_LEN - 1);
                        size_t o0 = ((size_t)b * D_DIM + col_g) * S_LEN + s;
                        size_t o1 = o0 + S_LEN;
                        g_vt_hi[o0] = h0; g_vt_lo[o0] = l0;
                        g_vt_hi[o1] = h1; g_vt_lo[o1] = l1;
                    }
                } else if (MODE == 1) {
                    float2 v; v.x = f0 * 0.03125f; v.y = f1 * 0.03125f;
                    *reinterpret_cast<float2*>(
                        &g_s[((size_t)z * S_LEN + row_g) * S_LEN + col_g]) = v;
                } else {
                    float2 v; v.x = f0; v.y = f1;
                    *reinterpret_cast<float2*>(
                        &out[((size_t)z * S_LEN + row_g) * D_DIM + col_g]) = v;
                }
            }
        }
    }
}

// ---------------------------------------------------------------------------
// fp32 -> bf16 hi/lo splitter
// ---------------------------------------------------------------------------
__global__ __launch_bounds__(256) void split_kernel(
    const float* __restrict__ src, __nv_bfloat16* __restrict__ hi,
    __nv_bfloat16* __restrict__ lo, int n4)
{
    int i = blockIdx.x * blockDim.x + threadIdx.x;
    if (i >= n4) return;
    float4 f = reinterpret_cast<const float4*>(src)[i];
    __nv_bfloat16 h0, l0, h1, l1, h2, l2, h3, l3;
    split2(f.x, h0, l0); split2(f.y, h1, l1);
    split2(f.z, h2, l2); split2(f.w, h3, l3);
    __nv_bfloat162 a, b, c, d;
    a.x = h0; a.y = h1; b.x = h2; b.y = h3;
    c.x = l0; c.y = l1; d.x = l2; d.y = l3;
    reinterpret_cast<__nv_bfloat162*>(hi)[i * 2]     = a;
    reinterpret_cast<__nv_bfloat162*>(hi)[i * 2 + 1] = b;
    reinterpret_cast<__nv_bfloat162*>(lo)[i * 2]     = c;
    reinterpret_cast<__nv_bfloat162*>(lo)[i * 2 + 1] = d;
}

// ---------------------------------------------------------------------------
// softmax: fp32 scores row -> bf16 hi/lo probs
// ---------------------------------------------------------------------------
__global__ __launch_bounds__(256) void softmax_kernel()
{
    const size_t row = blockIdx.x;
    const float* p = g_s + row * (size_t)S_LEN;
    const int tid = threadIdx.x;
    const int lane = tid & 31;
    const int wid = tid >> 5;

    float4 v[4];
    float mx = -CUDART_INF_F;
    #pragma unroll
    for (int i = 0; i < 4; ++i) {
        v[i] = reinterpret_cast<const float4*>(p)[tid + i * 256];
        mx = fmaxf(mx, fmaxf(fmaxf(v[i].x, v[i].y), fmaxf(v[i].z, v[i].w)));
    }
    #pragma unroll
    for (int o = 16; o > 0; o >>= 1)
        mx = fmaxf(mx, __shfl_xor_sync(0xFFFFFFFFu, mx, o));

    __shared__ float smax[8], ssum[8], sbc[2];
    if (lane == 0) smax[wid] = mx;
    __syncthreads();
    if (tid == 0) {
        float m = smax[0];
        #pragma unroll
        for (int i = 1; i < 8; ++i) m = fmaxf(m, smax[i]);
        sbc[0] = m;
    }
    __syncthreads();
    mx = sbc[0];

    float sum = 0.0f;
    #pragma unroll
    for (int i = 0; i < 4; ++i) {
        v[i].x = __expf(v[i].x - mx); v[i].y = __expf(v[i].y - mx);
        v[i].z = __expf(v[i].z - mx); v[i].w = __expf(v[i].w - mx);
        sum += v[i].x + v[i].y + v[i].z + v[i].w;
    }
    #pragma unroll
    for (int o = 16; o > 0; o >>= 1)
        sum += __shfl_xor_sync(0xFFFFFFFFu, sum, o);
    if (lane == 0) ssum[wid] = sum;
    __syncthreads();
    if (tid == 0) {
        float s = 0.0f;
        #pragma unroll
        for (int i = 0; i < 8; ++i) s += ssum[i];
        sbc[1] = 1.0f / s;
    }
    __syncthreads();
    const float inv = sbc[1];

    #pragma unroll
    for (int i = 0; i < 4; ++i) {
        float f0 = v[i].x * inv, f1 = v[i].y * inv, f2 = v[i].z * inv, f3 = v[i].w * inv;
        __nv_bfloat16 h0, l0, h1, l1, h2, l2, h3, l3;
        split2(f0, h0, l0); split2(f1, h1, l1);
        split2(f2, h2, l2); split2(f3, h3, l3);
        size_t o = row * (size_t)S_LEN + (size_t)(tid + i * 256) * 4;
        __nv_bfloat162 a, b, c, d;
        a.x = h0; a.y = h1; b.x = h2; b.y = h3;
        c.x = l0; c.y = l1; d.x = l2; d.y = l3;
        *reinterpret_cast<__nv_bfloat162*>(&g_p_hi[o])     = a;
        *reinterpret_cast<__nv_bfloat162*>(&g_p_hi[o + 2]) = b;
        *reinterpret_cast<__nv_bfloat162*>(&g_p_lo[o])     = c;
        *reinterpret_cast<__nv_bfloat162*>(&g_p_lo[o + 2]) = d;
    }
}

// ---------------------------------------------------------------------------
extern "C" void kernel_launch(void* const* d_in, const int* in_sizes, int n_in,
                              void* d_out, int out_size)
{
    const float* x  = (const float*)d_in[0];
    const float* Wq = (const float*)d_in[1];
    const float* bq = (const float*)d_in[2];
    const float* Wk = (const float*)d_in[3];
    const float* bk = (const float*)d_in[4];
    const float* Wv = (const float*)d_in[5];
    const float* bv = (const float*)d_in[6];
    float* out = (float*)d_out;

    cudaFuncSetAttribute(mm_kernel<0>, cudaFuncAttributeMaxDynamicSharedMemorySize, SMEM_TOTAL);
    cudaFuncSetAttribute(mm_kernel<1>, cudaFuncAttributeMaxDynamicSharedMemorySize, SMEM_TOTAL);
    cudaFuncSetAttribute(mm_kernel<2>, cudaFuncAttributeMaxDynamicSharedMemorySize, SMEM_TOTAL);

    __nv_bfloat16 *xh, *xl, *wqh, *wql, *wkh, *wkl, *wvh, *wvl;
    cudaGetSymbolAddress((void**)&xh,  g_x_hi);
    cudaGetSymbolAddress((void**)&xl,  g_x_lo);
    cudaGetSymbolAddress((void**)&wqh, g_wq_hi);
    cudaGetSymbolAddress((void**)&wql, g_wq_lo);
    cudaGetSymbolAddress((void**)&wkh, g_wk_hi);
    cudaGetSymbolAddress((void**)&wkl, g_wk_lo);
    cudaGetSymbolAddress((void**)&wvh, g_wv_hi);
    cudaGetSymbolAddress((void**)&wvl, g_wv_lo);

    const int nx = M_QKV * D_DIM / 4;   // float4 count
    const int nw = D_DIM * D_DIM / 4;
    split_kernel<<<nx / 256, 256>>>(x,  xh,  xl,  nx);
    split_kernel<<<nw / 256, 256>>>(Wq, wqh, wql, nw);
    split_kernel<<<nw / 256, 256>>>(Wk, wkh, wkl, nw);
    split_kernel<<<nw / 256, 256>>>(Wv, wvh, wvl, nw);

    dim3 blk(256);
    dim3 g0(D_DIM / 128, M_QKV / 128, 3);
    mm_kernel<0><<<g0, blk, SMEM_TOTAL>>>(bq, bk, bv, out);

    dim3 g1(S_LEN / 128, S_LEN / 128, B_SZ);
    mm_kernel<1><<<g1, blk, SMEM_TOTAL>>>(bq, bk, bv, out);

    softmax_kernel<<<B_SZ * S_LEN, 256>>>();

    dim3 g2(D_DIM / 128, S_LEN / 128, B_SZ);
    mm_kernel<2><<<g2, blk, SMEM_TOTAL>>>(bq, bk, bv, out);
}

// round 6
// speedup vs baseline: 4.7786x; 2.0673x over previous
#include <cuda_runtime.h>
#include <cuda_fp16.h>
#include <cstdint>
#include <math_constants.h>

#define B_SZ   4
#define S_LEN  4096
#define D_DIM  1024
#define M_QKV  (B_SZ * S_LEN)   // 16384

// ---------------------------------------------------------------------------
// Scratch (__device__ globals; allocation-free rule)
// ---------------------------------------------------------------------------
__device__ __half g_x [(size_t)M_QKV * D_DIM];
__device__ __half g_wq[(size_t)D_DIM * D_DIM];
__device__ __half g_wk[(size_t)D_DIM * D_DIM];
__device__ __half g_wv[(size_t)D_DIM * D_DIM];
__device__ __half g_q [(size_t)M_QKV * D_DIM];
__device__ __half g_k [(size_t)M_QKV * D_DIM];
__device__ __half g_vt[(size_t)B_SZ * D_DIM * S_LEN];   // [B][D][S]
__device__ float  g_s [(size_t)B_SZ * S_LEN * S_LEN];   // fp32 scores
__device__ __half g_p [(size_t)B_SZ * S_LEN * S_LEN];   // fp16 probs

// ---------------------------------------------------------------------------
// helpers
// ---------------------------------------------------------------------------
__device__ __forceinline__ uint32_t smem_u32(const void* p) {
    uint32_t a;
    asm("{ .reg .u64 t; cvta.to.shared.u64 t, %1; cvt.u32.u64 %0, t; }"
        : "=r"(a) : "l"(p));
    return a;
}

__device__ __forceinline__ void cp16(uint32_t dst, const void* src) {
    asm volatile("cp.async.cg.shared.global [%0], [%1], 16;"
                 :: "r"(dst), "l"(src) : "memory");
}
#define CP_COMMIT() asm volatile("cp.async.commit_group;" ::: "memory")

__device__ __forceinline__ void ldmx4(uint32_t& r0, uint32_t& r1,
                                      uint32_t& r2, uint32_t& r3, uint32_t addr) {
    asm volatile("ldmatrix.sync.aligned.m8n8.x4.shared.b16 {%0,%1,%2,%3}, [%4];"
                 : "=r"(r0), "=r"(r1), "=r"(r2), "=r"(r3) : "r"(addr));
}

__device__ __forceinline__ void mma_f16(float& c0, float& c1, float& c2, float& c3,
                                        uint32_t a0, uint32_t a1, uint32_t a2, uint32_t a3,
                                        uint32_t b0, uint32_t b1) {
    asm volatile(
        "mma.sync.aligned.m16n8k16.row.col.f32.f16.f16.f32 "
        "{%0,%1,%2,%3}, {%4,%5,%6,%7}, {%8,%9}, {%0,%1,%2,%3};"
        : "+f"(c0), "+f"(c1), "+f"(c2), "+f"(c3)
        : "r"(a0), "r"(a1), "r"(a2), "r"(a3), "r"(b0), "r"(b1));
}

// ---------------------------------------------------------------------------
// GEMM: C[128,128] per CTA = A[M,K] * B[N,K]^T  (fp16 in, fp32 accum)
// 8 warps (2x4), warp tile 64x32, BK=64, 3-stage cp.async pipeline.
// SMEM tile: 128 rows x 64 half (128B data), padded row stride 144B
// (144 mod 128 = 16 -> 8 consecutive rows hit 8 distinct 16B segments:
//  conflict-free ldmatrix).
// MODE 0: qkv (z: 0=q,1=k,2=v), 1: scores, 2: pv
// ---------------------------------------------------------------------------
#define ROW_B   144
#define TILE_B  (128 * ROW_B)        // 18432
#define STAGE_B (2 * TILE_B)         // 36864  (A, B)
#define NSTAGE  3
#define SMEM_TOTAL (NSTAGE * STAGE_B)  // 110592

template <int MODE>
__global__ __launch_bounds__(256, 1)
void mm_kernel(const float* __restrict__ bq, const float* __restrict__ bk,
               const float* __restrict__ bv, float* __restrict__ out)
{
    extern __shared__ char smem[];
    const uint32_t sb = smem_u32(smem);
    const int tid  = threadIdx.x;
    const int wid  = tid >> 5;
    const int lane = tid & 31;
    const int bx = blockIdx.x, by = blockIdx.y, z = blockIdx.z;

    const int rowA = by * 128;
    const int rowB = bx * 128;

    const __half *A, *B;
    int K;
    if (MODE == 0) {
        A = g_x;
        B = (z == 0) ? g_wq : (z == 1) ? g_wk : g_wv;
        K = D_DIM;
    } else if (MODE == 1) {
        A = g_q + (size_t)z * S_LEN * D_DIM;
        B = g_k + (size_t)z * S_LEN * D_DIM;
        K = D_DIM;
    } else {
        A = g_p  + (size_t)z * S_LEN * S_LEN;
        B = g_vt + (size_t)z * D_DIM * S_LEN;
        K = S_LEN;
    }

    const int nslab = K >> 6;          // K/64

    // ------------------ loader ------------------
    // 256 threads: 2 threads/row, each does 4 x 16B per tile.
    const int lr = tid >> 1;           // 0..127
    const int s4 = (tid & 1) * 4;      // first 16B segment (of 8 per row)
    auto load_slab = [&](int i) {
        const uint32_t stage = sb + (uint32_t)(i % NSTAGE) * STAGE_B;
        const size_t koff = (size_t)i * 64;
        const __half* srcA = A + (size_t)(rowA + lr) * K + koff + s4 * 8;
        const __half* srcB = B + (size_t)(rowB + lr) * K + koff + s4 * 8;
        const uint32_t dA = stage + (uint32_t)lr * ROW_B + (uint32_t)s4 * 16;
        const uint32_t dB = dA + TILE_B;
        #pragma unroll
        for (int j = 0; j < 4; ++j) cp16(dA + j * 16, srcA + j * 8);
        #pragma unroll
        for (int j = 0; j < 4; ++j) cp16(dB + j * 16, srcB + j * 8);
        CP_COMMIT();
    };

    // ------------------ fragments ------------------
    const int warp_m = wid >> 2;       // 0..1
    const int warp_n = wid & 3;        // 0..3
    const int mat    = lane >> 3;      // 0..3
    const int mrow   = lane & 7;

    const uint32_t a_off = (uint32_t)(((mat & 1) * 8 + mrow) * ROW_B + (mat >> 1) * 16);
    const uint32_t b_off = (uint32_t)(((mat >> 1) * 8 + mrow) * ROW_B + (mat & 1) * 16);

    float acc[4][4][4];
    #pragma unroll
    for (int mi = 0; mi < 4; ++mi)
        #pragma unroll
        for (int ni = 0; ni < 4; ++ni)
            #pragma unroll
            for (int r = 0; r < 4; ++r) acc[mi][ni][r] = 0.0f;

    load_slab(0);
    load_slab(1);

    for (int i = 0; i < nslab; ++i) {
        if (i + 1 < nslab) asm volatile("cp.async.wait_group 1;" ::: "memory");
        else               asm volatile("cp.async.wait_group 0;" ::: "memory");
        __syncthreads();
        // Safe without trailing barrier: every warp passed this sync only after
        // finishing its reads of stage (i-1)%3 == (i+2)%3 in iteration i-1.
        if (i + 2 < nslab) load_slab(i + 2);

        const uint32_t stage = sb + (uint32_t)(i % NSTAGE) * STAGE_B;
        const uint32_t aBase = stage + (uint32_t)(warp_m * 64) * ROW_B;
        const uint32_t bBase = stage + TILE_B + (uint32_t)(warp_n * 32) * ROW_B;

        #pragma unroll
        for (int ks = 0; ks < 4; ++ks) {
            uint32_t a[4][4], b[4][2];
            #pragma unroll
            for (int mi = 0; mi < 4; ++mi)
                ldmx4(a[mi][0], a[mi][1], a[mi][2], a[mi][3],
                      aBase + (uint32_t)(mi * 16) * ROW_B + (uint32_t)ks * 32 + a_off);
            #pragma unroll
            for (int n2 = 0; n2 < 2; ++n2)
                ldmx4(b[n2 * 2][0], b[n2 * 2][1], b[n2 * 2 + 1][0], b[n2 * 2 + 1][1],
                      bBase + (uint32_t)(n2 * 16) * ROW_B + (uint32_t)ks * 32 + b_off);
            #pragma unroll
            for (int mi = 0; mi < 4; ++mi)
                #pragma unroll
                for (int ni = 0; ni < 4; ++ni) {
                    float* c = acc[mi][ni];
                    mma_f16(c[0], c[1], c[2], c[3],
                            a[mi][0], a[mi][1], a[mi][2], a[mi][3],
                            b[ni][0], b[ni][1]);
                }
        }
    }

    // ------------------ epilogue (from registers) ------------------
    const float* bias = (MODE == 0) ? ((z == 0) ? bq : (z == 1) ? bk : bv) : nullptr;
    __half* dq = (MODE == 0) ? ((z == 0) ? g_q : g_k) : nullptr;

    #pragma unroll
    for (int mi = 0; mi < 4; ++mi) {
        #pragma unroll
        for (int ni = 0; ni < 4; ++ni) {
            #pragma unroll
            for (int h = 0; h < 2; ++h) {
                const int row_g = rowA + warp_m * 64 + mi * 16 + (lane >> 2) + h * 8;
                const int col_g = rowB + warp_n * 32 + ni * 8 + 2 * (lane & 3);
                float f0 = acc[mi][ni][h * 2];
                float f1 = acc[mi][ni][h * 2 + 1];

                if (MODE == 0) {
                    f0 += bias[col_g];
                    f1 += bias[col_g + 1];
                    if (z < 2) {
                        __half2 hv;
                        hv.x = __float2half_rn(f0);
                        hv.y = __float2half_rn(f1);
                        *reinterpret_cast<__half2*>(
                            &dq[(size_t)row_g * D_DIM + col_g]) = hv;
                    } else {
                        const int b = row_g >> 12;
                        const int s = row_g & (S_LEN - 1);
                        size_t o0 = ((size_t)b * D_DIM + col_g) * S_LEN + s;
                        g_vt[o0]         = __float2half_rn(f0);
                        g_vt[o0 + S_LEN] = __float2half_rn(f1);
                    }
                } else if (MODE == 1) {
                    float2 v; v.x = f0 * 0.03125f; v.y = f1 * 0.03125f;
                    *reinterpret_cast<float2*>(
                        &g_s[((size_t)z * S_LEN + row_g) * S_LEN + col_g]) = v;
                } else {
                    float2 v; v.x = f0; v.y = f1;
                    *reinterpret_cast<float2*>(
                        &out[((size_t)z * S_LEN + row_g) * D_DIM + col_g]) = v;
                }
            }
        }
    }
}

// ---------------------------------------------------------------------------
// fp32 -> fp16 converter
// ---------------------------------------------------------------------------
__global__ __launch_bounds__(256) void conv_kernel(
    const float* __restrict__ src, __half* __restrict__ dst, int n4)
{
    int i = blockIdx.x * blockDim.x + threadIdx.x;
    if (i >= n4) return;
    float4 f = reinterpret_cast<const float4*>(src)[i];
    __half2 a, b;
    a.x = __float2half_rn(f.x); a.y = __float2half_rn(f.y);
    b.x = __float2half_rn(f.z); b.y = __float2half_rn(f.w);
    reinterpret_cast<__half2*>(dst)[i * 2]     = a;
    reinterpret_cast<__half2*>(dst)[i * 2 + 1] = b;
}

// ---------------------------------------------------------------------------
// softmax: fp32 scores row -> fp16 probs
// ---------------------------------------------------------------------------
__global__ __launch_bounds__(256) void softmax_kernel()
{
    const size_t row = blockIdx.x;
    const float* p = g_s + row * (size_t)S_LEN;
    const int tid = threadIdx.x;
    const int lane = tid & 31;
    const int wid = tid >> 5;

    float4 v[4];
    float mx = -CUDART_INF_F;
    #pragma unroll
    for (int i = 0; i < 4; ++i) {
        v[i] = reinterpret_cast<const float4*>(p)[tid + i * 256];
        mx = fmaxf(mx, fmaxf(fmaxf(v[i].x, v[i].y), fmaxf(v[i].z, v[i].w)));
    }
    #pragma unroll
    for (int o = 16; o > 0; o >>= 1)
        mx = fmaxf(mx, __shfl_xor_sync(0xFFFFFFFFu, mx, o));

    __shared__ float smax[8], ssum[8], sbc[2];
    if (lane == 0) smax[wid] = mx;
    __syncthreads();
    if (tid == 0) {
        float m = smax[0];
        #pragma unroll
        for (int i = 1; i < 8; ++i) m = fmaxf(m, smax[i]);
        sbc[0] = m;
    }
    __syncthreads();
    mx = sbc[0];

    float sum = 0.0f;
    #pragma unroll
    for (int i = 0; i < 4; ++i) {
        v[i].x = __expf(v[i].x - mx); v[i].y = __expf(v[i].y - mx);
        v[i].z = __expf(v[i].z - mx); v[i].w = __expf(v[i].w - mx);
        sum += v[i].x + v[i].y + v[i].z + v[i].w;
    }
    #pragma unroll
    for (int o = 16; o > 0; o >>= 1)
        sum += __shfl_xor_sync(0xFFFFFFFFu, sum, o);
    if (lane == 0) ssum[wid] = sum;
    __syncthreads();
    if (tid == 0) {
        float s = 0.0f;
        #pragma unroll
        for (int i = 0; i < 8; ++i) s += ssum[i];
        sbc[1] = 1.0f / s;
    }
    __syncthreads();
    const float inv = sbc[1];

    #pragma unroll
    for (int i = 0; i < 4; ++i) {
        __half2 a, b;
        a.x = __float2half_rn(v[i].x * inv);
        a.y = __float2half_rn(v[i].y * inv);
        b.x = __float2half_rn(v[i].z * inv);
        b.y = __float2half_rn(v[i].w * inv);
        size_t o = row * (size_t)S_LEN + (size_t)(tid + i * 256) * 4;
        *reinterpret_cast<__half2*>(&g_p[o])     = a;
        *reinterpret_cast<__half2*>(&g_p[o + 2]) = b;
    }
}

// ---------------------------------------------------------------------------
extern "C" void kernel_launch(void* const* d_in, const int* in_sizes, int n_in,
                              void* d_out, int out_size)
{
    const float* x  = (const float*)d_in[0];
    const float* Wq = (const float*)d_in[1];
    const float* bq = (const float*)d_in[2];
    const float* Wk = (const float*)d_in[3];
    const float* bk = (const float*)d_in[4];
    const float* Wv = (const float*)d_in[5];
    const float* bv = (const float*)d_in[6];
    float* out = (float*)d_out;

    cudaFuncSetAttribute(mm_kernel<0>, cudaFuncAttributeMaxDynamicSharedMemorySize, SMEM_TOTAL);
    cudaFuncSetAttribute(mm_kernel<1>, cudaFuncAttributeMaxDynamicSharedMemorySize, SMEM_TOTAL);
    cudaFuncSetAttribute(mm_kernel<2>, cudaFuncAttributeMaxDynamicSharedMemorySize, SMEM_TOTAL);

    __half *xh, *wqh, *wkh, *wvh;
    cudaGetSymbolAddress((void**)&xh,  g_x);
    cudaGetSymbolAddress((void**)&wqh, g_wq);
    cudaGetSymbolAddress((void**)&wkh, g_wk);
    cudaGetSymbolAddress((void**)&wvh, g_wv);

    const int nx = M_QKV * D_DIM / 4;   // float4 count
    const int nw = D_DIM * D_DIM / 4;
    conv_kernel<<<nx / 256, 256>>>(x,  xh,  nx);
    conv_kernel<<<nw / 256, 256>>>(Wq, wqh, nw);
    conv_kernel<<<nw / 256, 256>>>(Wk, wkh, nw);
    conv_kernel<<<nw / 256, 256>>>(Wv, wvh, nw);

    dim3 blk(256);
    dim3 g0(D_DIM / 128, M_QKV / 128, 3);
    mm_kernel<0><<<g0, blk, SMEM_TOTAL>>>(bq, bk, bv, out);

    dim3 g1(S_LEN / 128, S_LEN / 128, B_SZ);
    mm_kernel<1><<<g1, blk, SMEM_TOTAL>>>(bq, bk, bv, out);

    softmax_kernel<<<B_SZ * S_LEN, 256>>>();

    dim3 g2(D_DIM / 128, S_LEN / 128, B_SZ);
    mm_kernel<2><<<g2, blk, SMEM_TOTAL>>>(bq, bk, bv, out);
}

// round 7
// speedup vs baseline: 5.7162x; 1.1962x over previous
#include <cuda_runtime.h>
#include <cuda_fp16.h>
#include <cstdint>
#include <math_constants.h>

#define B_SZ   4
#define S_LEN  4096
#define D_DIM  1024
#define M_QKV  (B_SZ * S_LEN)   // 16384

// ---------------------------------------------------------------------------
// Scratch (__device__ globals; allocation-free rule)
// ---------------------------------------------------------------------------
__device__ __half g_x [(size_t)M_QKV * D_DIM];
__device__ __half g_wq[(size_t)D_DIM * D_DIM];
__device__ __half g_wk[(size_t)D_DIM * D_DIM];
__device__ __half g_wv[(size_t)D_DIM * D_DIM];
__device__ __half g_q [(size_t)M_QKV * D_DIM];
__device__ __half g_k [(size_t)M_QKV * D_DIM];
__device__ __half g_vt[(size_t)B_SZ * D_DIM * S_LEN];   // [B][D][S]
__device__ float  g_s [(size_t)B_SZ * S_LEN * S_LEN];   // fp32 scores
__device__ __half g_p [(size_t)B_SZ * S_LEN * S_LEN];   // fp16 probs

// ---------------------------------------------------------------------------
// helpers
// ---------------------------------------------------------------------------
__device__ __forceinline__ uint32_t smem_u32(const void* p) {
    uint32_t a;
    asm("{ .reg .u64 t; cvta.to.shared.u64 t, %1; cvt.u32.u64 %0, t; }"
        : "=r"(a) : "l"(p));
    return a;
}

__device__ __forceinline__ void cp16(uint32_t dst, const void* src) {
    asm volatile("cp.async.cg.shared.global [%0], [%1], 16;"
                 :: "r"(dst), "l"(src) : "memory");
}
#define CP_COMMIT() asm volatile("cp.async.commit_group;" ::: "memory")

__device__ __forceinline__ void ldmx4(uint32_t& r0, uint32_t& r1,
                                      uint32_t& r2, uint32_t& r3, uint32_t addr) {
    asm volatile("ldmatrix.sync.aligned.m8n8.x4.shared.b16 {%0,%1,%2,%3}, [%4];"
                 : "=r"(r0), "=r"(r1), "=r"(r2), "=r"(r3) : "r"(addr));
}

__device__ __forceinline__ void mma_f16(float& c0, float& c1, float& c2, float& c3,
                                        uint32_t a0, uint32_t a1, uint32_t a2, uint32_t a3,
                                        uint32_t b0, uint32_t b1) {
    asm volatile(
        "mma.sync.aligned.m16n8k16.row.col.f32.f16.f16.f32 "
        "{%0,%1,%2,%3}, {%4,%5,%6,%7}, {%8,%9}, {%0,%1,%2,%3};"
        : "+f"(c0), "+f"(c1), "+f"(c2), "+f"(c3)
        : "r"(a0), "r"(a1), "r"(a2), "r"(a3), "r"(b0), "r"(b1));
}

// ---------------------------------------------------------------------------
// GEMM: C[256,128] per CTA = A[M,K] * B[N,K]^T  (fp16 in, fp32 accum)
// 16 warps (4x4), warp tile 64x32, BK=64, 3-stage cp.async pipeline.
// SMEM rows padded to 144B stride (conflict-free ldmatrix).
// MODE 0: qkv (z: 0=q,1=k,2=v), 1: scores, 2: pv
// ---------------------------------------------------------------------------
#define ROW_B    144
#define TILE_A_B (256 * ROW_B)       // 36864
#define TILE_B_B (128 * ROW_B)       // 18432
#define STAGE_B  (TILE_A_B + TILE_B_B)  // 55296
#define NSTAGE   3
#define SMEM_TOTAL (NSTAGE * STAGE_B)   // 165888

template <int MODE>
__global__ __launch_bounds__(512, 1)
void mm_kernel(const float* __restrict__ bq, const float* __restrict__ bk,
               const float* __restrict__ bv, float* __restrict__ out)
{
    extern __shared__ char smem[];
    const uint32_t sb = smem_u32(smem);
    const int tid  = threadIdx.x;
    const int wid  = tid >> 5;
    const int lane = tid & 31;
    const int bx = blockIdx.x, by = blockIdx.y, z = blockIdx.z;

    const int rowA = by * 256;
    const int rowB = bx * 128;

    const __half *A, *B;
    int K;
    if (MODE == 0) {
        A = g_x;
        B = (z == 0) ? g_wq : (z == 1) ? g_wk : g_wv;
        K = D_DIM;
    } else if (MODE == 1) {
        A = g_q + (size_t)z * S_LEN * D_DIM;
        B = g_k + (size_t)z * S_LEN * D_DIM;
        K = D_DIM;
    } else {
        A = g_p  + (size_t)z * S_LEN * S_LEN;
        B = g_vt + (size_t)z * D_DIM * S_LEN;
        K = S_LEN;
    }

    const int nslab = K >> 6;          // K/64

    // ------------------ loader (512 threads) ------------------
    // A: 256 rows x 8 segs(16B) -> 2 thr/row, 4 segs each
    // B: 128 rows x 8 segs      -> 4 thr/row, 2 segs each
    const int lrA = tid >> 1;          // 0..255
    const int sA  = (tid & 1) * 4;     // seg 0 or 4
    const int lrB = tid >> 2;          // 0..127
    const int sB  = (tid & 3) * 2;     // seg 0,2,4,6
    auto load_slab = [&](int i) {
        const uint32_t stage = sb + (uint32_t)(i % NSTAGE) * STAGE_B;
        const size_t koff = (size_t)i * 64;
        const __half* srcA = A + (size_t)(rowA + lrA) * K + koff + sA * 8;
        const uint32_t dA = stage + (uint32_t)lrA * ROW_B + (uint32_t)sA * 16;
        #pragma unroll
        for (int j = 0; j < 4; ++j) cp16(dA + j * 16, srcA + j * 8);
        const __half* srcB = B + (size_t)(rowB + lrB) * K + koff + sB * 8;
        const uint32_t dB = stage + TILE_A_B + (uint32_t)lrB * ROW_B + (uint32_t)sB * 16;
        #pragma unroll
        for (int j = 0; j < 2; ++j) cp16(dB + j * 16, srcB + j * 8);
        CP_COMMIT();
    };

    // ------------------ fragments ------------------
    const int warp_m = wid >> 2;       // 0..3 (64 rows each)
    const int warp_n = wid & 3;        // 0..3 (32 cols each)
    const int mat    = lane >> 3;      // 0..3
    const int mrow   = lane & 7;

    const uint32_t a_off = (uint32_t)(((mat & 1) * 8 + mrow) * ROW_B + (mat >> 1) * 16);
    const uint32_t b_off = (uint32_t)(((mat >> 1) * 8 + mrow) * ROW_B + (mat & 1) * 16);

    float acc[4][4][4];
    #pragma unroll
    for (int mi = 0; mi < 4; ++mi)
        #pragma unroll
        for (int ni = 0; ni < 4; ++ni)
            #pragma unroll
            for (int r = 0; r < 4; ++r) acc[mi][ni][r] = 0.0f;

    load_slab(0);
    load_slab(1);

    for (int i = 0; i < nslab; ++i) {
        if (i + 1 < nslab) asm volatile("cp.async.wait_group 1;" ::: "memory");
        else               asm volatile("cp.async.wait_group 0;" ::: "memory");
        __syncthreads();
        // Stage reuse safe: sync(i) implies all warps finished reads of
        // stage (i+2)%3 during iteration i-1.
        if (i + 2 < nslab) load_slab(i + 2);

        const uint32_t stage = sb + (uint32_t)(i % NSTAGE) * STAGE_B;
        const uint32_t aBase = stage + (uint32_t)(warp_m * 64) * ROW_B;
        const uint32_t bBase = stage + TILE_A_B + (uint32_t)(warp_n * 32) * ROW_B;

        #pragma unroll
        for (int ks = 0; ks < 4; ++ks) {
            uint32_t a[4][4], b[4][2];
            #pragma unroll
            for (int mi = 0; mi < 4; ++mi)
                ldmx4(a[mi][0], a[mi][1], a[mi][2], a[mi][3],
                      aBase + (uint32_t)(mi * 16) * ROW_B + (uint32_t)ks * 32 + a_off);
            #pragma unroll
            for (int n2 = 0; n2 < 2; ++n2)
                ldmx4(b[n2 * 2][0], b[n2 * 2][1], b[n2 * 2 + 1][0], b[n2 * 2 + 1][1],
                      bBase + (uint32_t)(n2 * 16) * ROW_B + (uint32_t)ks * 32 + b_off);
            #pragma unroll
            for (int mi = 0; mi < 4; ++mi)
                #pragma unroll
                for (int ni = 0; ni < 4; ++ni) {
                    float* c = acc[mi][ni];
                    mma_f16(c[0], c[1], c[2], c[3],
                            a[mi][0], a[mi][1], a[mi][2], a[mi][3],
                            b[ni][0], b[ni][1]);
                }
        }
    }

    // ------------------ epilogue (from registers) ------------------
    const float* bias = (MODE == 0) ? ((z == 0) ? bq : (z == 1) ? bk : bv) : nullptr;
    __half* dq = (MODE == 0) ? ((z == 0) ? g_q : g_k) : nullptr;

    #pragma unroll
    for (int mi = 0; mi < 4; ++mi) {
        #pragma unroll
        for (int ni = 0; ni < 4; ++ni) {
            #pragma unroll
            for (int h = 0; h < 2; ++h) {
                const int row_g = rowA + warp_m * 64 + mi * 16 + (lane >> 2) + h * 8;
                const int col_g = rowB + warp_n * 32 + ni * 8 + 2 * (lane & 3);
                float f0 = acc[mi][ni][h * 2];
                float f1 = acc[mi][ni][h * 2 + 1];

                if (MODE == 0) {
                    f0 += bias[col_g];
                    f1 += bias[col_g + 1];
                    if (z < 2) {
                        __half2 hv;
                        hv.x = __float2half_rn(f0);
                        hv.y = __float2half_rn(f1);
                        *reinterpret_cast<__half2*>(
                            &dq[(size_t)row_g * D_DIM + col_g]) = hv;
                    } else {
                        const int b = row_g >> 12;
                        const int s = row_g & (S_LEN - 1);
                        size_t o0 = ((size_t)b * D_DIM + col_g) * S_LEN + s;
                        g_vt[o0]         = __float2half_rn(f0);
                        g_vt[o0 + S_LEN] = __float2half_rn(f1);
                    }
                } else if (MODE == 1) {
                    float2 v; v.x = f0 * 0.03125f; v.y = f1 * 0.03125f;
                    *reinterpret_cast<float2*>(
                        &g_s[((size_t)z * S_LEN + row_g) * S_LEN + col_g]) = v;
                } else {
                    float2 v; v.x = f0; v.y = f1;
                    *reinterpret_cast<float2*>(
                        &out[((size_t)z * S_LEN + row_g) * D_DIM + col_g]) = v;
                }
            }
        }
    }
}

// ---------------------------------------------------------------------------
// fp32 -> fp16 converter
// ---------------------------------------------------------------------------
__global__ __launch_bounds__(256) void conv_kernel(
    const float* __restrict__ src, __half* __restrict__ dst, int n4)
{
    int i = blockIdx.x * blockDim.x + threadIdx.x;
    if (i >= n4) return;
    float4 f = reinterpret_cast<const float4*>(src)[i];
    __half2 a, b;
    a.x = __float2half_rn(f.x); a.y = __float2half_rn(f.y);
    b.x = __float2half_rn(f.z); b.y = __float2half_rn(f.w);
    reinterpret_cast<__half2*>(dst)[i * 2]     = a;
    reinterpret_cast<__half2*>(dst)[i * 2 + 1] = b;
}

// ---------------------------------------------------------------------------
// softmax: fp32 scores row -> fp16 probs
// ---------------------------------------------------------------------------
__global__ __launch_bounds__(256) void softmax_kernel()
{
    const size_t row = blockIdx.x;
    const float* p = g_s + row * (size_t)S_LEN;
    const int tid = threadIdx.x;
    const int lane = tid & 31;
    const int wid = tid >> 5;

    float4 v[4];
    float mx = -CUDART_INF_F;
    #pragma unroll
    for (int i = 0; i < 4; ++i) {
        v[i] = reinterpret_cast<const float4*>(p)[tid + i * 256];
        mx = fmaxf(mx, fmaxf(fmaxf(v[i].x, v[i].y), fmaxf(v[i].z, v[i].w)));
    }
    #pragma unroll
    for (int o = 16; o > 0; o >>= 1)
        mx = fmaxf(mx, __shfl_xor_sync(0xFFFFFFFFu, mx, o));

    __shared__ float smax[8], ssum[8], sbc[2];
    if (lane == 0) smax[wid] = mx;
    __syncthreads();
    if (tid == 0) {
        float m = smax[0];
        #pragma unroll
        for (int i = 1; i < 8; ++i) m = fmaxf(m, smax[i]);
        sbc[0] = m;
    }
    __syncthreads();
    mx = sbc[0];

    float sum = 0.0f;
    #pragma unroll
    for (int i = 0; i < 4; ++i) {
        v[i].x = __expf(v[i].x - mx); v[i].y = __expf(v[i].y - mx);
        v[i].z = __expf(v[i].z - mx); v[i].w = __expf(v[i].w - mx);
        sum += v[i].x + v[i].y + v[i].z + v[i].w;
    }
    #pragma unroll
    for (int o = 16; o > 0; o >>= 1)
        sum += __shfl_xor_sync(0xFFFFFFFFu, sum, o);
    if (lane == 0) ssum[wid] = sum;
    __syncthreads();
    if (tid == 0) {
        float s = 0.0f;
        #pragma unroll
        for (int i = 0; i < 8; ++i) s += ssum[i];
        sbc[1] = 1.0f / s;
    }
    __syncthreads();
    const float inv = sbc[1];

    #pragma unroll
    for (int i = 0; i < 4; ++i) {
        __half2 a, b;
        a.x = __float2half_rn(v[i].x * inv);
        a.y = __float2half_rn(v[i].y * inv);
        b.x = __float2half_rn(v[i].z * inv);
        b.y = __float2half_rn(v[i].w * inv);
        size_t o = row * (size_t)S_LEN + (size_t)(tid + i * 256) * 4;
        *reinterpret_cast<__half2*>(&g_p[o])     = a;
        *reinterpret_cast<__half2*>(&g_p[o + 2]) = b;
    }
}

// ---------------------------------------------------------------------------
extern "C" void kernel_launch(void* const* d_in, const int* in_sizes, int n_in,
                              void* d_out, int out_size)
{
    const float* x  = (const float*)d_in[0];
    const float* Wq = (const float*)d_in[1];
    const float* bq = (const float*)d_in[2];
    const float* Wk = (const float*)d_in[3];
    const float* bk = (const float*)d_in[4];
    const float* Wv = (const float*)d_in[5];
    const float* bv = (const float*)d_in[6];
    float* out = (float*)d_out;

    cudaFuncSetAttribute(mm_kernel<0>, cudaFuncAttributeMaxDynamicSharedMemorySize, SMEM_TOTAL);
    cudaFuncSetAttribute(mm_kernel<1>, cudaFuncAttributeMaxDynamicSharedMemorySize, SMEM_TOTAL);
    cudaFuncSetAttribute(mm_kernel<2>, cudaFuncAttributeMaxDynamicSharedMemorySize, SMEM_TOTAL);

    __half *xh, *wqh, *wkh, *wvh;
    cudaGetSymbolAddress((void**)&xh,  g_x);
    cudaGetSymbolAddress((void**)&wqh, g_wq);
    cudaGetSymbolAddress((void**)&wkh, g_wk);
    cudaGetSymbolAddress((void**)&wvh, g_wv);

    const int nx = M_QKV * D_DIM / 4;   // float4 count
    const int nw = D_DIM * D_DIM / 4;
    conv_kernel<<<nx / 256, 256>>>(x,  xh,  nx);
    conv_kernel<<<nw / 256, 256>>>(Wq, wqh, nw);
    conv_kernel<<<nw / 256, 256>>>(Wk, wkh, nw);
    conv_kernel<<<nw / 256, 256>>>(Wv, wvh, nw);

    dim3 blk(512);
    dim3 g0(D_DIM / 128, M_QKV / 256, 3);
    mm_kernel<0><<<g0, blk, SMEM_TOTAL>>>(bq, bk, bv, out);

    dim3 g1(S_LEN / 128, S_LEN / 256, B_SZ);
    mm_kernel<1><<<g1, blk, SMEM_TOTAL>>>(bq, bk, bv, out);

    softmax_kernel<<<B_SZ * S_LEN, 256>>>();

    dim3 g2(D_DIM / 128, S_LEN / 256, B_SZ);
    mm_kernel<2><<<g2, blk, SMEM_TOTAL>>>(bq, bk, bv, out);
}